// round 15
// baseline (speedup 1.0000x reference)
#include <cuda_runtime.h>

// Problem constants (from reference): B=128, S=256, D=1024, BETA=1.0
#define BB 128
#define SS 256
#define DD 1024
#define BETA_F 1.0f

#define NSM 148
#define OCC_MAIN 4
#define WARPS 4                          // warps per block (128 threads)
#define NTHREADS (WARPS * 32)            // 128
#define NBLOCKS (NSM * OCC_MAIN)         // 592 — one exact wave at occ=4
#define NPAIRS (NBLOCKS * 2)             // 1184 warp-pairs
#define NROWS (SS - 2)                   // 254 interior rows per batch
#define TOTAL_Q (BB * NROWS)             // 32512 queries
#define MAXQ 30                          // max queries per pair (28 actual)

__device__ float g_partials[NBLOCKS];
__device__ unsigned g_ctr = 0;           // self-resetting via atomicInc wrap

// Consume row r from (PX,NX); refill slot j with row r+2's loads right after
// consuming it (issue-to-consume distance = 2 row periods, both streams).
#define ROW_BODY(PX, NX)                                                      \
    do {                                                                      \
        const int rp = r + 2;                                                 \
        const bool hp = rp < r1;                                              \
        const float4* ppn = base;                                             \
        const float4* npn = base;                                             \
        if (hp) {                                                             \
            ppn = (const float4*)(bridges + ((size_t)b * SS + rp + 1) * DD)   \
                  + hoff;                                                     \
            const int ni = neg_i[b * NROWS + rp];                             \
            const int nj = neg_j[b * NROWS + rp];                             \
            npn = (const float4*)(bridges + ((size_t)ni * SS + nj) * DD)      \
                  + hoff;                                                     \
        }                                                                     \
        float accA = 0.0f, accBh = 0.0f, accBt = 0.0f;                        \
        _Pragma("unroll")                                                     \
        for (int j = 0; j < 4; j++) {                                         \
            const float4 pv = PX[j], nv = NX[j];                              \
            if (hp) {                                                         \
                PX[j] = ppn[lane + j * 32];                                   \
                NX[j] = npn[lane + j * 32];                                   \
            }                                                                 \
            const float4 hv = h[j], tv = tl[j];                               \
            const float dx = nv.x - pv.x, sx = nv.x + pv.x;                   \
            const float dy = nv.y - pv.y, sy = nv.y + pv.y;                   \
            const float dz = nv.z - pv.z, sz = nv.z + pv.z;                   \
            const float dw = nv.w - pv.w, sw = nv.w + pv.w;                   \
            accA  = fmaf(sx,   dx, accA);                                     \
            accBh = fmaf(hv.x, dx, accBh);                                    \
            accBt = fmaf(tv.x, dx, accBt);                                    \
            accA  = fmaf(sy,   dy, accA);                                     \
            accBh = fmaf(hv.y, dy, accBh);                                    \
            accBt = fmaf(tv.y, dy, accBt);                                    \
            accA  = fmaf(sz,   dz, accA);                                     \
            accBh = fmaf(hv.z, dz, accBh);                                    \
            accBt = fmaf(tv.z, dz, accBt);                                    \
            accA  = fmaf(sw,   dw, accA);                                     \
            accBh = fmaf(hv.w, dw, accBh);                                    \
            accBt = fmaf(tv.w, dw, accBt);                                    \
        }                                                                     \
        _Pragma("unroll")                                                     \
        for (int off = 16; off; off >>= 1) {                                  \
            accA  += __shfl_xor_sync(0xffffffffu, accA,  off);                \
            accBh += __shfl_xor_sync(0xffffffffu, accBh, off);                \
            accBt += __shfl_xor_sync(0xffffffffu, accBt, off);                \
        }                                                                     \
        if (lane == 0) {                                                      \
            const int slot = b * NROWS + r - pair_start;                      \
            sm[slot][half][0] = accA;                                         \
            sm[slot][half][1] = accBh;                                        \
            sm[slot][half][2] = accBt;                                        \
        }                                                                     \
    } while (0)

// Stream rows [r0, r1) of batch b, D-half 'half'. Dist-2 on both streams.
__device__ __forceinline__ void process_segment(
    const float* __restrict__ bridges,
    const int*   __restrict__ neg_i,
    const int*   __restrict__ neg_j,
    float (*sm)[2][3],                  // [slot][half][A,Bh,Bt]
    int pair_start, int half, int b, int r0, int r1, int lane)
{
    const float4* base = (const float4*)(bridges + (size_t)b * SS * DD);
    const int hoff = half * 128;                  // float4 offset of this half

    // own-batch head/tail halves, register-resident (mandatory per R3/R8)
    float4 h[4], tl[4];
    {
        const float4* hp  = base + hoff;
        const float4* tp4 = base + (size_t)(SS - 1) * (DD / 4) + hoff;
#pragma unroll
        for (int j = 0; j < 4; j++) {
            h[j]  = hp [lane + j * 32];
            tl[j] = tp4[lane + j * 32];
        }
    }

    float4 PA[4], NA[4], PB[4], NB[4];

    // prologue: row r0 -> (PA,NA), row r0+1 -> (PB,NB)
    {
        const float4* pp =
            (const float4*)(bridges + ((size_t)b * SS + r0 + 1) * DD) + hoff;
        const int ni = neg_i[b * NROWS + r0];
        const int nj = neg_j[b * NROWS + r0];
        const float4* np =
            (const float4*)(bridges + ((size_t)ni * SS + nj) * DD) + hoff;
#pragma unroll
        for (int j = 0; j < 4; j++) {
            PA[j] = pp[lane + j * 32];
            NA[j] = np[lane + j * 32];
        }
    }
    if (r0 + 1 < r1) {
        const float4* pp =
            (const float4*)(bridges + ((size_t)b * SS + r0 + 2) * DD) + hoff;
        const int ni = neg_i[b * NROWS + r0 + 1];
        const int nj = neg_j[b * NROWS + r0 + 1];
        const float4* np =
            (const float4*)(bridges + ((size_t)ni * SS + nj) * DD) + hoff;
#pragma unroll
        for (int j = 0; j < 4; j++) {
            PB[j] = pp[lane + j * 32];
            NB[j] = np[lane + j * 32];
        }
    }

    int r = r0;
    while (true) {
        ROW_BODY(PA, NA);               // row r; refill A with row r+2
        r++;
        if (r >= r1) break;
        ROW_BODY(PB, NB);               // row r; refill B with row r+2
        r++;
        if (r >= r1) break;
    }
}

__global__ __launch_bounds__(NTHREADS, OCC_MAIN)
void bridge_loss_paired2(const float* __restrict__ bridges,
                         const int*   __restrict__ b_inx,
                         const int*   __restrict__ neg_i,
                         const int*   __restrict__ neg_j,
                         float*       __restrict__ out)
{
    const int warp = threadIdx.x >> 5;
    const int lane = threadIdx.x & 31;
    const int pairLocal = warp >> 1;              // 0..1
    const int half      = warp & 1;               // D-half owned by this warp
    const int gp = blockIdx.x * 2 + pairLocal;    // 0..1183

    __shared__ float sm_part[2][MAXQ][2][3];      // [pair][slot][half][A,Bh,Bt]
    __shared__ float pair_loss[2];
    __shared__ bool  amLast;

    // balanced contiguous query chunk for this pair (both halves walk it)
    const int pair_start = (int)(((long long)gp       * TOTAL_Q) / NPAIRS);
    const int pair_end   = (int)(((long long)(gp + 1) * TOTAL_Q) / NPAIRS);

    int s = pair_start;
    while (s < pair_end) {
        const int b  = s / NROWS;
        const int r0 = s - b * NROWS;
        const int r1 = min(pair_end - b * NROWS, NROWS);
        process_segment(bridges, neg_i, neg_j, sm_part[pairLocal],
                        pair_start, half, b, r0, r1, lane);
        s = b * NROWS + r1;
    }

    __syncthreads();

    // combine: even warp of each pair, one lane per query
    if (half == 0) {
        const int len = pair_end - pair_start;    // <= 28
        float v = 0.0f;
        if (lane < len) {
            const int q = pair_start + lane;
            const int b = q / NROWS;
            const int r = q - b * NROWS;
            const float th = (float)b_inx[b * SS];
            const float tt = (float)b_inx[b * SS + SS - 1];
            const float tp = (float)b_inx[b * SS + r + 1];
            const float alpha = (tp - th) / (tt - th);
            const float sigma = alpha * (tt - tp);
            const float inv   = 1.0f / (2.0f * sigma * sigma);

            const float A  = sm_part[pairLocal][lane][0][0] + sm_part[pairLocal][lane][1][0];
            const float Bh = sm_part[pairLocal][lane][0][1] + sm_part[pairLocal][lane][1][1];
            const float Bt = sm_part[pairLocal][lane][0][2] + sm_part[pairLocal][lane][1][2];

            const float mdot = fmaf(alpha, Bt, (1.0f - alpha) * Bh);
            const float diff = fmaf(-2.0f, mdot, A);
            const float cur  = fmaf(diff, inv, BETA_F);
            v = cur > 0.0f ? cur : 0.0f;
        }
#pragma unroll
        for (int off = 16; off; off >>= 1)
            v += __shfl_xor_sync(0xffffffffu, v, off);
        if (lane == 0) pair_loss[pairLocal] = v;
    }
    __syncthreads();

    if (threadIdx.x == 0) {
        g_partials[blockIdx.x] = pair_loss[0] + pair_loss[1];
        __threadfence();
        unsigned old = atomicInc(&g_ctr, NBLOCKS - 1);   // wraps -> replay safe
        amLast = (old == NBLOCKS - 1);
    }
    __syncthreads();

    if (amLast) {
        __shared__ float fin[NTHREADS];
        float t = 0.0f;
#pragma unroll
        for (int k = 0; k < (NBLOCKS + NTHREADS - 1) / NTHREADS; k++) {
            const int idx = threadIdx.x + k * NTHREADS;
            if (idx < NBLOCKS) t += g_partials[idx];
        }
        fin[threadIdx.x] = t;
        __syncthreads();
#pragma unroll
        for (int st = NTHREADS / 2; st > 0; st >>= 1) {
            if ((int)threadIdx.x < st) fin[threadIdx.x] += fin[threadIdx.x + st];
            __syncthreads();
        }
        if (threadIdx.x == 0) out[0] = fin[0] / (float)BB;
    }
}

extern "C" void kernel_launch(void* const* d_in, const int* in_sizes, int n_in,
                              void* d_out, int out_size)
{
    const float* bridges = (const float*)d_in[0];
    const int*   b_inx   = (const int*)  d_in[1];
    const int*   neg_i   = (const int*)  d_in[2];
    const int*   neg_j   = (const int*)  d_in[3];

    bridge_loss_paired2<<<NBLOCKS, NTHREADS>>>(bridges, b_inx, neg_i, neg_j,
                                               (float*)d_out);
}

// round 17
// speedup vs baseline: 1.2119x; 1.2119x over previous
#include <cuda_runtime.h>
#include <cuda_pipeline_primitives.h>

// Problem constants (from reference): B=128, S=256, D=1024, BETA=1.0
#define BB 128
#define SS 256
#define DD 1024
#define BETA_F 1.0f

#define NSM 148
#define OCC_MAIN 4
#define WARPS 4                          // warps per block (128 threads)
#define NTHREADS (WARPS * 32)            // 128
#define NBLOCKS (NSM * OCC_MAIN)         // 592 — one exact wave at occ=4
#define NPAIRS (NBLOCKS * 2)             // 1184 warp-pairs
#define NROWS (SS - 2)                   // 254 interior rows per batch
#define TOTAL_Q (BB * NROWS)             // 32512 queries
#define MAXQ 30                          // max queries per pair (28 actual)

#define DEPTH 2                          // cp.async stages per warp
#define STAGE_F4 256                     // 128 float4 pos-half + 128 neg-half

__device__ float g_partials[NBLOCKS];
__device__ unsigned g_ctr = 0;           // self-resetting via atomicInc wrap

// Issue one row (pos half + neg half, 4 KB) into stage buffer 'dst'.
__device__ __forceinline__ void issue_row(float4* dst, const float4* pos,
                                          const float4* neg, int lane)
{
#pragma unroll
    for (int j = 0; j < 4; j++)
        __pipeline_memcpy_async(dst + lane + j * 32,       pos + lane + j * 32, 16);
#pragma unroll
    for (int j = 0; j < 4; j++)
        __pipeline_memcpy_async(dst + 128 + lane + j * 32, neg + lane + j * 32, 16);
}

// Stream rows [r0, r1) of batch b, D-half 'half', through a DEPTH-stage ring.
__device__ __forceinline__ void process_segment(
    const float* __restrict__ bridges,
    const int*   __restrict__ neg_i,
    const int*   __restrict__ neg_j,
    float (*sm)[2][3],                  // [slot][half][A,Bh,Bt]
    float4 (*stage)[STAGE_F4],          // this warp's DEPTH stages
    int pair_start, int half, int b, int r0, int r1, int lane)
{
    const float4* base = (const float4*)(bridges + (size_t)b * SS * DD);
    const int hoff = half * 128;                  // float4 offset of this half

    // own-batch head/tail halves, register-resident (mandatory per R3/R8)
    float4 h[4], tl[4];
    {
        const float4* hp  = base + hoff;
        const float4* tp4 = base + (size_t)(SS - 1) * (DD / 4) + hoff;
#pragma unroll
        for (int j = 0; j < 4; j++) {
            h[j]  = hp [lane + j * 32];
            tl[j] = tp4[lane + j * 32];
        }
    }

    // prologue: stage k <- row r0+k (commit empty groups past the end to keep
    // the group-accounting uniform)
#pragma unroll
    for (int k = 0; k < DEPTH; k++) {
        const int rr = r0 + k;
        if (rr < r1) {
            const float4* pp =
                (const float4*)(bridges + ((size_t)b * SS + rr + 1) * DD) + hoff;
            const int ni = neg_i[b * NROWS + rr];
            const int nj = neg_j[b * NROWS + rr];
            const float4* np =
                (const float4*)(bridges + ((size_t)ni * SS + nj) * DD) + hoff;
            issue_row(stage[k], pp, np, lane);
        }
        __pipeline_commit();
    }

    int r = r0, s = 0;
    while (r < r1) {
        // refill-row indices early (tiny L2-hot loads overlap the wait)
        const int rp = r + DEPTH;
        const bool hp_ = rp < r1;
        int ni = 0, nj = 0;
        if (hp_) { ni = neg_i[b * NROWS + rp]; nj = neg_j[b * NROWS + rp]; }

        __pipeline_wait_prior(DEPTH - 1);         // stage s (row r) complete

        float4 P[4], N[4];
#pragma unroll
        for (int j = 0; j < 4; j++) {
            P[j] = stage[s][lane + j * 32];
            N[j] = stage[s][128 + lane + j * 32];
        }

        // refill stage s with row r+DEPTH (consume LDS already issued in-order
        // before these async writes can land)
        if (hp_) {
            const float4* pp =
                (const float4*)(bridges + ((size_t)b * SS + rp + 1) * DD) + hoff;
            const float4* np =
                (const float4*)(bridges + ((size_t)ni * SS + nj) * DD) + hoff;
            issue_row(stage[s], pp, np, lane);
        }
        __pipeline_commit();

        // A = sum (n^2 - p^2); Bh = sum h*(n-p); Bt = sum t*(n-p)
        float accA = 0.0f, accBh = 0.0f, accBt = 0.0f;
#pragma unroll
        for (int j = 0; j < 4; j++) {
            const float4 pv = P[j], nv = N[j];
            const float4 hv = h[j], tv = tl[j];
            const float dx = nv.x - pv.x, sx = nv.x + pv.x;
            const float dy = nv.y - pv.y, sy = nv.y + pv.y;
            const float dz = nv.z - pv.z, sz = nv.z + pv.z;
            const float dw = nv.w - pv.w, sw = nv.w + pv.w;
            accA  = fmaf(sx,   dx, accA);
            accBh = fmaf(hv.x, dx, accBh);
            accBt = fmaf(tv.x, dx, accBt);
            accA  = fmaf(sy,   dy, accA);
            accBh = fmaf(hv.y, dy, accBh);
            accBt = fmaf(tv.y, dy, accBt);
            accA  = fmaf(sz,   dz, accA);
            accBh = fmaf(hv.z, dz, accBh);
            accBt = fmaf(tv.z, dz, accBt);
            accA  = fmaf(sw,   dw, accA);
            accBh = fmaf(hv.w, dw, accBh);
            accBt = fmaf(tv.w, dw, accBt);
        }

#pragma unroll
        for (int off = 16; off; off >>= 1) {
            accA  += __shfl_xor_sync(0xffffffffu, accA,  off);
            accBh += __shfl_xor_sync(0xffffffffu, accBh, off);
            accBt += __shfl_xor_sync(0xffffffffu, accBt, off);
        }
        if (lane == 0) {
            const int slot = b * NROWS + r - pair_start;
            sm[slot][half][0] = accA;
            sm[slot][half][1] = accBh;
            sm[slot][half][2] = accBt;
        }

        s ^= 1;
        r++;
    }
}

__global__ __launch_bounds__(NTHREADS, OCC_MAIN)
void bridge_loss_cp2(const float* __restrict__ bridges,
                     const int*   __restrict__ b_inx,
                     const int*   __restrict__ neg_i,
                     const int*   __restrict__ neg_j,
                     float*       __restrict__ out)
{
    const int warp = threadIdx.x >> 5;
    const int lane = threadIdx.x & 31;
    const int pairLocal = warp >> 1;              // 0..1
    const int half      = warp & 1;               // D-half owned by this warp
    const int gp = blockIdx.x * 2 + pairLocal;    // 0..1183

    __shared__ float4 stage_mem[WARPS][DEPTH][STAGE_F4];   // 32 KB static
    __shared__ float  sm_part[2][MAXQ][2][3];     // [pair][slot][half][A,Bh,Bt]
    __shared__ float  pair_loss[2];
    __shared__ bool   amLast;

    const int pair_start = (int)(((long long)gp       * TOTAL_Q) / NPAIRS);
    const int pair_end   = (int)(((long long)(gp + 1) * TOTAL_Q) / NPAIRS);

    int s = pair_start;
    while (s < pair_end) {
        const int b  = s / NROWS;
        const int r0 = s - b * NROWS;
        const int r1 = min(pair_end - b * NROWS, NROWS);
        process_segment(bridges, neg_i, neg_j, sm_part[pairLocal],
                        stage_mem[warp], pair_start, half, b, r0, r1, lane);
        s = b * NROWS + r1;
    }

    __syncthreads();

    // combine: even warp of each pair, one lane per query
    if (half == 0) {
        const int len = pair_end - pair_start;    // <= 28
        float v = 0.0f;
        if (lane < len) {
            const int q = pair_start + lane;
            const int b = q / NROWS;
            const int r = q - b * NROWS;
            const float th = (float)b_inx[b * SS];
            const float tt = (float)b_inx[b * SS + SS - 1];
            const float tp = (float)b_inx[b * SS + r + 1];
            const float alpha = (tp - th) / (tt - th);
            const float sigma = alpha * (tt - tp);
            const float inv   = 1.0f / (2.0f * sigma * sigma);

            const float A  = sm_part[pairLocal][lane][0][0] + sm_part[pairLocal][lane][1][0];
            const float Bh = sm_part[pairLocal][lane][0][1] + sm_part[pairLocal][lane][1][1];
            const float Bt = sm_part[pairLocal][lane][0][2] + sm_part[pairLocal][lane][1][2];

            const float mdot = fmaf(alpha, Bt, (1.0f - alpha) * Bh);
            const float diff = fmaf(-2.0f, mdot, A);
            const float cur  = fmaf(diff, inv, BETA_F);
            v = cur > 0.0f ? cur : 0.0f;
        }
#pragma unroll
        for (int off = 16; off; off >>= 1)
            v += __shfl_xor_sync(0xffffffffu, v, off);
        if (lane == 0) pair_loss[pairLocal] = v;
    }
    __syncthreads();

    if (threadIdx.x == 0) {
        g_partials[blockIdx.x] = pair_loss[0] + pair_loss[1];
        __threadfence();
        unsigned old = atomicInc(&g_ctr, NBLOCKS - 1);   // wraps -> replay safe
        amLast = (old == NBLOCKS - 1);
    }
    __syncthreads();

    if (amLast) {
        __shared__ float fin[NTHREADS];
        float t = 0.0f;
#pragma unroll
        for (int k = 0; k < (NBLOCKS + NTHREADS - 1) / NTHREADS; k++) {
            const int idx = threadIdx.x + k * NTHREADS;
            if (idx < NBLOCKS) t += g_partials[idx];
        }
        fin[threadIdx.x] = t;
        __syncthreads();
#pragma unroll
        for (int st = NTHREADS / 2; st > 0; st >>= 1) {
            if ((int)threadIdx.x < st) fin[threadIdx.x] += fin[threadIdx.x + st];
            __syncthreads();
        }
        if (threadIdx.x == 0) out[0] = fin[0] / (float)BB;
    }
}

extern "C" void kernel_launch(void* const* d_in, const int* in_sizes, int n_in,
                              void* d_out, int out_size)
{
    const float* bridges = (const float*)d_in[0];
    const int*   b_inx   = (const int*)  d_in[1];
    const int*   neg_i   = (const int*)  d_in[2];
    const int*   neg_j   = (const int*)  d_in[3];

    bridge_loss_cp2<<<NBLOCKS, NTHREADS>>>(bridges, b_inx, neg_i, neg_j,
                                           (float*)d_out);
}